// round 1
// baseline (speedup 1.0000x reference)
#include <cuda_runtime.h>
#include <cstdint>

#define NSEG   512
#define HID    512
#define GOALD  128
#define INDIM  640
#define BLOCK  256
#define MROWS  512          // nodes per block (2 per thread)
#define KT     32           // k tile
#define XPAD   36           // padded row stride (words) -> conflict-free LDS.128
#define NTILES (INDIM / KT)
#define SMEM_BYTES ((MROWS * XPAD + KT * 16) * 4)

typedef unsigned long long u64;

__device__ float    g_sum[NSEG];
__device__ float    g_cnt[NSEG];
__device__ unsigned g_max[NSEG];

__device__ __forceinline__ void ffma2(u64 &acc, u64 a, u64 b) {
    asm("fma.rn.f32x2 %0, %1, %2, %0;" : "+l"(acc) : "l"(a), "l"(b));
}
__device__ __forceinline__ u64 pk2(float v) {
    u64 r; asm("mov.b64 %0, {%1, %1};" : "=l"(r) : "f"(v)); return r;
}
__device__ __forceinline__ float2 upk(u64 v) {
    float2 f; asm("mov.b64 {%0, %1}, %2;" : "=f"(f.x), "=f"(f.y) : "l"(v)); return f;
}

__global__ void init_kernel() {
    int i = threadIdx.x;
    if (i < NSEG) { g_sum[i] = 0.f; g_cnt[i] = 0.f; g_max[i] = 0u; }
}

__global__ __launch_bounds__(BLOCK) void mlp_seg_kernel(
    const float* __restrict__ nodes, const float* __restrict__ goal,
    const int* __restrict__ segids,
    const float* __restrict__ W1, const float* __restrict__ b1,
    const float* __restrict__ W2, const float* __restrict__ b2,
    int N)
{
    extern __shared__ float smem[];
    float* xs = smem;                    // [MROWS][XPAD]
    float* ws = smem + MROWS * XPAD;     // [KT][16]
    const int t    = threadIdx.x;
    const int base = blockIdx.x * MROWS;

    u64 accA[8], accB[8];
#pragma unroll
    for (int p = 0; p < 8; ++p) { accA[p] = 0ull; accB[p] = 0ull; }

    for (int tile = 0; tile < NTILES; ++tile) {
        const int k0 = tile * KT;

        // --- stage W tile: KT*16 = 512 contiguous floats ---
        if (t < 128)
            ((float4*)ws)[t] = ((const float4*)(W1 + k0 * 16))[t];

        // --- stage x tile: 512 rows x 32 floats, coalesced (8 thr/row) ---
        const float* src; int stride, kloc;
        if (k0 < HID) { src = nodes; stride = HID;   kloc = k0; }
        else          { src = goal;  stride = GOALD; kloc = k0 - HID; }
#pragma unroll
        for (int pass = 0; pass < 16; ++pass) {
            int row  = pass * 32 + (t >> 3);
            int c4   = (t & 7) * 4;
            int node = base + row;
            float4 v = make_float4(0.f, 0.f, 0.f, 0.f);
            if (node < N)
                v = *(const float4*)(src + (size_t)node * stride + kloc + c4);
            *(float4*)(xs + row * XPAD + c4) = v;
        }
        __syncthreads();

        // --- compute: per thread, 2 nodes x KT k's x 16 j's ---
#pragma unroll
        for (int kk = 0; kk < KT; kk += 4) {
            float4 xa = *(const float4*)(xs + t * XPAD + kk);
            float4 xb = *(const float4*)(xs + (t + BLOCK) * XPAD + kk);
#pragma unroll
            for (int r = 0; r < 4; ++r) {
                const ulonglong2* wr = (const ulonglong2*)(ws + (kk + r) * 16);
                ulonglong2 q0 = wr[0], q1 = wr[1], q2 = wr[2], q3 = wr[3];
                float fa = (r == 0) ? xa.x : (r == 1) ? xa.y : (r == 2) ? xa.z : xa.w;
                float fb = (r == 0) ? xb.x : (r == 1) ? xb.y : (r == 2) ? xb.z : xb.w;
                u64 va = pk2(fa), vb = pk2(fb);
                ffma2(accA[0], va, q0.x); ffma2(accA[1], va, q0.y);
                ffma2(accA[2], va, q1.x); ffma2(accA[3], va, q1.y);
                ffma2(accA[4], va, q2.x); ffma2(accA[5], va, q2.y);
                ffma2(accA[6], va, q3.x); ffma2(accA[7], va, q3.y);
                ffma2(accB[0], vb, q0.x); ffma2(accB[1], vb, q0.y);
                ffma2(accB[2], vb, q1.x); ffma2(accB[3], vb, q1.y);
                ffma2(accB[4], vb, q2.x); ffma2(accB[5], vb, q2.y);
                ffma2(accB[6], vb, q3.x); ffma2(accB[7], vb, q3.y);
            }
        }
        __syncthreads();
    }

    // --- epilogue: bias + relu + W2 dot, then segment atomics ---
    float w2r[16], b1r[16];
#pragma unroll
    for (int j = 0; j < 16; ++j) { b1r[j] = b1[j]; w2r[j] = W2[j]; }
    const float bias2 = b2[0];

    auto emit = [&](int node, u64* acc) {
        if (node >= N) return;
        float out = bias2;
#pragma unroll
        for (int p = 0; p < 8; ++p) {
            float2 a = upk(acc[p]);
            float h0 = fmaxf(a.x + b1r[2 * p],     0.f);
            float h1 = fmaxf(a.y + b1r[2 * p + 1], 0.f);
            out += h0 * w2r[2 * p] + h1 * w2r[2 * p + 1];
        }
        int seg = segids[node];
        atomicAdd(&g_sum[seg], out);
        atomicAdd(&g_cnt[seg], 1.f);
        unsigned b  = __float_as_uint(out);
        unsigned e  = (b & 0x80000000u) ? ~b : (b | 0x80000000u);
        atomicMax(&g_max[seg], e);
    };
    emit(base + t,         accA);
    emit(base + t + BLOCK, accB);
}

__global__ void finalize_kernel(float* __restrict__ out) {
    int s = threadIdx.x;
    if (s < NSEG) {
        float mean = g_sum[s] / fmaxf(g_cnt[s], 1.f);
        unsigned u = g_max[s];
        float mx = (u & 0x80000000u) ? __uint_as_float(u ^ 0x80000000u)
                                     : __uint_as_float(~u);
        out[s] = mx * 0.5f + mean * 0.5f;
    }
}

extern "C" void kernel_launch(void* const* d_in, const int* in_sizes, int n_in,
                              void* d_out, int out_size) {
    const float* nodes  = (const float*)d_in[0];
    const float* goal   = (const float*)d_in[1];
    const int*   segids = (const int*)d_in[2];
    // num_segments may or may not be materialized as an input tensor
    int iW = (in_sizes[3] == INDIM * 16) ? 3 : 4;
    const float* W1 = (const float*)d_in[iW];
    const float* b1 = (const float*)d_in[iW + 1];
    const float* W2 = (const float*)d_in[iW + 2];
    const float* b2 = (const float*)d_in[iW + 3];
    const int N = in_sizes[2];

    cudaFuncSetAttribute(mlp_seg_kernel,
                         cudaFuncAttributeMaxDynamicSharedMemorySize, SMEM_BYTES);

    init_kernel<<<1, NSEG>>>();
    int grid = (N + MROWS - 1) / MROWS;
    mlp_seg_kernel<<<grid, BLOCK, SMEM_BYTES>>>(nodes, goal, segids,
                                                W1, b1, W2, b2, N);
    finalize_kernel<<<1, NSEG>>>((float*)d_out);
}